// round 6
// baseline (speedup 1.0000x reference)
#include <cuda_runtime.h>

#define H     1024
#define HH    (H * H)
#define P     (3 * HH)
#define P4    (P / 4)
#define HH4   (HH / 4)
#define NBINS 256
#define NIDX  400000

#define HBLK  200     // hist/scat blocks
#define BATCH 8       // samples per thread  (200*256*8 = 409600 >= NIDX)

// ---------------- device scratch (no allocation allowed) ----------------
__device__ int      g_hist[6 * NBINS];
__device__ float    g_tab[3][NBINS];      // table[b]/255 per channel
__device__ double   g_acc;
__device__ unsigned g_cnt_loss;
__device__ unsigned g_cnt_hist;
__device__ unsigned g_binD[HH];           // packed bins of ref_masked  (b0|b1<<8|b2<<16)
__device__ unsigned g_binR[HH];           // packed bins of target_masked

__device__ __forceinline__ float dn(float x) {
    float v = (x + 1.0f) * 0.5f;
    return fminf(fmaxf(v, 0.0f), 1.0f);
}

__device__ __forceinline__ int binof(float v255) {
    return min((int)v255, NBINS - 1);
}

// ---------------- kernel 1: elementwise transforms + bin packing ---------
// out planes: [0:P) target_masked/255, [P:2P) ref_masked/255,
//             [2P:3P) input_masked/255, [3P:4P) input_match base (= ref_masked/255)
__global__ void ew_k(const float4* __restrict__ inp, const float4* __restrict__ tgt,
                     const float4* __restrict__ ref, const float4* __restrict__ msrc,
                     const float4* __restrict__ mtar, float4* __restrict__ out) {
    if (blockIdx.x == 0) {
        for (int t = threadIdx.x; t < 6 * NBINS; t += blockDim.x) g_hist[t] = 0;
        if (threadIdx.x == 0) { g_acc = 0.0; g_cnt_loss = 0u; g_cnt_hist = 0u; }
    }
    int i = blockIdx.x * blockDim.x + threadIdx.x;   // pixel-group index [0, HH4)
    if (i >= HH4) return;
    float4 ms = msrc[i];
    float4 mt = mtar[i];
    float mu[4] = { ms.x != 0.0f ? 1.0f : 0.0f, ms.y != 0.0f ? 1.0f : 0.0f,
                    ms.z != 0.0f ? 1.0f : 0.0f, ms.w != 0.0f ? 1.0f : 0.0f };
    float tu[4] = { mt.x != 0.0f ? 1.0f : 0.0f, mt.y != 0.0f ? 1.0f : 0.0f,
                    mt.z != 0.0f ? 1.0f : 0.0f, mt.w != 0.0f ? 1.0f : 0.0f };
    unsigned pd[4] = {0, 0, 0, 0};
    unsigned pr[4] = {0, 0, 0, 0};
#pragma unroll
    for (int c = 0; c < 3; c++) {
        float4 t = tgt[c * HH4 + i];
        float4 r = ref[c * HH4 + i];
        float4 in = inp[c * HH4 + i];
        float to[4] = {dn(t.x), dn(t.y), dn(t.z), dn(t.w)};
        float ro[4] = {dn(r.x), dn(r.y), dn(r.z), dn(r.w)};
        float io[4] = {fminf(fmaxf(in.x, 0.0f), 1.0f), fminf(fmaxf(in.y, 0.0f), 1.0f),
                       fminf(fmaxf(in.z, 0.0f), 1.0f), fminf(fmaxf(in.w, 0.0f), 1.0f)};
        float4 otm, orm, oim;
        float* potm = (float*)&otm; float* porm = (float*)&orm; float* poim = (float*)&oim;
#pragma unroll
        for (int j = 0; j < 4; j++) {
            float rm = ro[j] * mu[j];
            float tm = to[j] * tu[j];
            potm[j] = tm;
            porm[j] = rm;
            poim[j] = io[j] * mu[j];
            pd[j] |= (unsigned)binof(rm * 255.0f) << (8 * c);
            pr[j] |= (unsigned)binof(tm * 255.0f) << (8 * c);
        }
        out[c * HH4 + i]          = otm;
        out[P4 + c * HH4 + i]     = orm;
        out[2 * P4 + c * HH4 + i] = oim;
        out[3 * P4 + c * HH4 + i] = orm;   // scatter overwrites selected pixels
    }
    ((uint4*)g_binD)[i] = make_uint4(pd[0], pd[1], pd[2], pd[3]);
    ((uint4*)g_binR)[i] = make_uint4(pr[0], pr[1], pr[2], pr[3]);
}

// ---------------- kernel 2: histograms (batched gathers) + CDF/table -----
__global__ void hist_k(const int* __restrict__ i0, const int* __restrict__ i1,
                       const int* __restrict__ i2, const int* __restrict__ i3) {
    __shared__ int sh[6 * NBINS];
    __shared__ bool last;
    for (int t = threadIdx.x; t < 6 * NBINS; t += blockDim.x) sh[t] = 0;
    __syncthreads();

    int base = blockIdx.x * blockDim.x * BATCH + threadIdx.x;
    unsigned bd[BATCH], br[BATCH];
    bool ok[BATCH];
    // phase 1: issue all gathers (MLP = 2*BATCH)
#pragma unroll
    for (int j = 0; j < BATCH; j++) {
        int k = base + j * blockDim.x;
        ok[j] = (k < NIDX);
        int kk = ok[j] ? k : 0;
        bd[j] = g_binD[i0[kk] * H + i1[kk]];
        br[j] = g_binR[i2[kk] * H + i3[kk]];
    }
    // phase 2: shared atomics
#pragma unroll
    for (int j = 0; j < BATCH; j++) {
        if (!ok[j]) continue;
        atomicAdd(&sh[bd[j] & 255u], 1);
        atomicAdd(&sh[NBINS + ((bd[j] >> 8) & 255u)], 1);
        atomicAdd(&sh[2 * NBINS + ((bd[j] >> 16) & 255u)], 1);
        atomicAdd(&sh[3 * NBINS + (br[j] & 255u)], 1);
        atomicAdd(&sh[4 * NBINS + ((br[j] >> 8) & 255u)], 1);
        atomicAdd(&sh[5 * NBINS + ((br[j] >> 16) & 255u)], 1);
    }
    __syncthreads();
    for (int t = threadIdx.x; t < 6 * NBINS; t += blockDim.x) {
        int v = sh[t];
        if (v) atomicAdd(&g_hist[t], v);
    }
    // last finishing block computes CDF + transfer table
    __threadfence();
    __syncthreads();
    if (threadIdx.x == 0)
        last = (atomicAdd(&g_cnt_hist, 1u) == gridDim.x - 1);
    __syncthreads();
    if (!last) return;

    __shared__ float cdf[6][NBINS];
    int b = threadIdx.x;   // 256 threads
    // counts are integers <= 400000 < 2^24: parallel scan is exact in f32
#pragma unroll
    for (int c = 0; c < 6; c++) cdf[c][b] = (float)g_hist[c * NBINS + b];
    __syncthreads();
    for (int off = 1; off < NBINS; off <<= 1) {
        float v[6];
#pragma unroll
        for (int c = 0; c < 6; c++) v[c] = (b >= off) ? cdf[c][b - off] : 0.0f;
        __syncthreads();
#pragma unroll
        for (int c = 0; c < 6; c++) cdf[c][b] += v[c];
        __syncthreads();
    }
#pragma unroll
    for (int c = 0; c < 6; c++) cdf[c][b] = __fdiv_rn(cdf[c][b], (float)NIDX);
    __syncthreads();
#pragma unroll
    for (int c = 0; c < 3; c++) {
        int tab;
        if (b == NBINS - 1) {
            tab = NBINS - 1;
        } else {
            tab = b;
            float r = cdf[c][b];
            const float* cr = cdf[3 + c];
            for (int j = 0; j < NBINS - 1; j++) {
                if (r >= cr[j] && r <= cr[j + 1]) { tab = j + 1; break; }
            }
        }
        g_tab[c][b] = __fdiv_rn((float)tab, 255.0f);
    }
}

// ---------------- kernel 3: scatter matched values (batched) --------------
__global__ void scat_k(const int* __restrict__ i0, const int* __restrict__ i1,
                       float* __restrict__ o_match) {
    __shared__ float stab[3][NBINS];
    {
        int t = threadIdx.x;
        stab[0][t] = g_tab[0][t];
        stab[1][t] = g_tab[1][t];
        stab[2][t] = g_tab[2][t];
    }
    __syncthreads();
    int base = blockIdx.x * blockDim.x * BATCH + threadIdx.x;
    int pd[BATCH];
    unsigned bd[BATCH];
    bool ok[BATCH];
#pragma unroll
    for (int j = 0; j < BATCH; j++) {
        int k = base + j * blockDim.x;
        ok[j] = (k < NIDX);
    }
#pragma unroll
    for (int j = 0; j < BATCH; j++) {
        int k = base + j * blockDim.x;
        int kk = ok[j] ? k : 0;
        pd[j] = i0[kk] * H + i1[kk];
        bd[j] = g_binD[pd[j]];
    }
#pragma unroll
    for (int j = 0; j < BATCH; j++) {
        if (!ok[j]) continue;
        o_match[pd[j]]          = stab[0][bd[j] & 255u];   // duplicates write identical values
        o_match[HH + pd[j]]     = stab[1][(bd[j] >> 8) & 255u];
        o_match[2 * HH + pd[j]] = stab[2][(bd[j] >> 16) & 255u];
    }
}

// ---------------- kernel 4: L1 mean reduction + finalize ------------------
__global__ void loss_k(const float4* __restrict__ a, const float4* __restrict__ b,
                       float* __restrict__ o_loss) {
    float local = 0.0f;
    for (int i = blockIdx.x * blockDim.x + threadIdx.x; i < P4;
         i += gridDim.x * blockDim.x) {
        float4 x = a[i], y = b[i];
        local += fabsf(x.x - y.x) + fabsf(x.y - y.y) +
                 fabsf(x.z - y.z) + fabsf(x.w - y.w);
    }
#pragma unroll
    for (int off = 16; off; off >>= 1) local += __shfl_down_sync(0xFFFFFFFFu, local, off);
    __shared__ float ws[8];
    __shared__ bool last;
    if ((threadIdx.x & 31) == 0) ws[threadIdx.x >> 5] = local;
    __syncthreads();
    if (threadIdx.x < 32) {
        float v = (threadIdx.x < (blockDim.x >> 5)) ? ws[threadIdx.x] : 0.0f;
#pragma unroll
        for (int off = 4; off; off >>= 1) v += __shfl_down_sync(0xFFFFFFFFu, v, off);
        if (threadIdx.x == 0) {
            atomicAdd(&g_acc, (double)v);
            __threadfence();
            last = (atomicAdd(&g_cnt_loss, 1u) == gridDim.x - 1);
        }
    }
    __syncthreads();
    if (last && threadIdx.x == 0) {
        double total = atomicAdd(&g_acc, 0.0);
        o_loss[0] = (float)(total / (double)P);
    }
}

// ---------------- launch -------------------------------------------------
extern "C" void kernel_launch(void* const* d_in, const int* in_sizes, int n_in,
                              void* d_out, int out_size) {
    const float* inp  = (const float*)d_in[0];
    const float* tgt  = (const float*)d_in[1];
    const float* ref  = (const float*)d_in[2];
    const float* msrc = (const float*)d_in[3];
    const float* mtar = (const float*)d_in[4];
    // d_in[5] = target_data_eye (unused by reference)
    const int* i0 = (const int*)d_in[6];
    const int* i1 = (const int*)d_in[7];
    const int* i2 = (const int*)d_in[8];
    const int* i3 = (const int*)d_in[9];
    float* out = (float*)d_out;

    ew_k<<<HH4 / 256, 256>>>((const float4*)inp, (const float4*)tgt,
                             (const float4*)ref, (const float4*)msrc,
                             (const float4*)mtar, (float4*)out);
    hist_k<<<HBLK, 256>>>(i0, i1, i2, i3);
    scat_k<<<HBLK, 256>>>(i0, i1, out + (size_t)3 * P);
    loss_k<<<148 * 4, 256>>>((const float4*)(out + (size_t)2 * P),
                             (const float4*)(out + (size_t)3 * P),
                             out + (size_t)4 * P);
}